// round 1
// baseline (speedup 1.0000x reference)
#include <cuda_runtime.h>
#include <cuda_bf16.h>

#define TBG 512
#define TIN 256
#define MROWS 2048   // B*N = 32*64

// Precomputed softmin weights: w[i][t], i in [0,256), t in [0,512)
__device__ float g_w[TIN * TBG];

// ---------------------------------------------------------------------------
// Kernel 1: t_weights = softmax(-b * |time_bg[t] - time_in[i]|) over t.
// One block per i (256 blocks), 256 threads, 2 t-values per thread.
// ---------------------------------------------------------------------------
__global__ void softmin_weights_kernel(const float* __restrict__ time_bg,
                                       const float* __restrict__ time_in,
                                       const float* __restrict__ bandwidth) {
    __shared__ float s_red[8];
    __shared__ float s_bcast;

    const int i   = blockIdx.x;
    const int tid = threadIdx.x;

    const float b  = fmaxf(bandwidth[0], 1e-6f);
    const float ti = time_in[i];

    const float x0 = b * fabsf(time_bg[tid]       - ti);
    const float x1 = b * fabsf(time_bg[tid + 256] - ti);

    // block-wide min(x)  (== max of -x for the stable softmax shift)
    float mn = fminf(x0, x1);
    #pragma unroll
    for (int o = 16; o > 0; o >>= 1)
        mn = fminf(mn, __shfl_xor_sync(0xffffffffu, mn, o));
    if ((tid & 31) == 0) s_red[tid >> 5] = mn;
    __syncthreads();
    if (tid == 0) {
        float v = s_red[0];
        #pragma unroll
        for (int w = 1; w < 8; w++) v = fminf(v, s_red[w]);
        s_bcast = v;
    }
    __syncthreads();
    const float xmin = s_bcast;

    const float e0 = __expf(xmin - x0);
    const float e1 = __expf(xmin - x1);

    // block-wide sum
    float sm = e0 + e1;
    #pragma unroll
    for (int o = 16; o > 0; o >>= 1)
        sm += __shfl_xor_sync(0xffffffffu, sm, o);
    if ((tid & 31) == 0) s_red[tid >> 5] = sm;
    __syncthreads();
    if (tid == 0) {
        float v = 0.0f;
        #pragma unroll
        for (int w = 0; w < 8; w++) v += s_red[w];
        s_bcast = v;
    }
    __syncthreads();

    const float inv = 1.0f / s_bcast;
    g_w[i * TBG + tid]       = e0 * inv;
    g_w[i * TBG + tid + 256] = e1 * inv;
}

// ---------------------------------------------------------------------------
// Kernel 2: C[m][i] = sum_t A[m][t] * w[i][t]
//   A: [2048, 512] row-major (K-contiguous), W: [256, 512] row-major.
// Tile: BM=64 x BI=64, BK=32, 256 threads, 4x4 microtile per thread.
// Grid: (256/64, 2048/64) = (4, 32) = 128 blocks ~= 1 per SM.
// ---------------------------------------------------------------------------
#define BM 64
#define BI 64
#define BK 32

__global__ void __launch_bounds__(256, 1)
smoother_gemm_kernel(const float* __restrict__ A, float* __restrict__ C) {
    __shared__ float As[BK][BM];
    __shared__ float Ws[BK][BI];

    const int tid = threadIdx.x;
    const int tx  = tid & 15;   // i direction (x4)
    const int ty  = tid >> 4;   // m direction (x4)

    const int m0 = blockIdx.y * BM;
    const int i0 = blockIdx.x * BI;

    // Tile-load mapping: thread loads one float4 along K for two rows.
    const int lm = tid >> 3;         // 0..31
    const int lk = (tid & 7) << 2;   // 0,4,...,28

    const float* Ap0 = A   + (m0 + lm)      * TBG + lk;
    const float* Ap1 = A   + (m0 + lm + 32) * TBG + lk;
    const float* Wp0 = g_w + (i0 + lm)      * TBG + lk;
    const float* Wp1 = g_w + (i0 + lm + 32) * TBG + lk;

    float acc[4][4] = {};

    for (int k0 = 0; k0 < TBG; k0 += BK) {
        // Global loads first (coalesced 128B per 4-row group).
        const float4 a0 = *(const float4*)(Ap0 + k0);
        const float4 a1 = *(const float4*)(Ap1 + k0);
        const float4 w0 = *(const float4*)(Wp0 + k0);
        const float4 w1 = *(const float4*)(Wp1 + k0);

        __syncthreads();  // previous iteration's smem reads done

        // Transposed store: As[k][m], Ws[k][i]
        As[lk + 0][lm] = a0.x; As[lk + 1][lm] = a0.y;
        As[lk + 2][lm] = a0.z; As[lk + 3][lm] = a0.w;
        As[lk + 0][lm + 32] = a1.x; As[lk + 1][lm + 32] = a1.y;
        As[lk + 2][lm + 32] = a1.z; As[lk + 3][lm + 32] = a1.w;

        Ws[lk + 0][lm] = w0.x; Ws[lk + 1][lm] = w0.y;
        Ws[lk + 2][lm] = w0.z; Ws[lk + 3][lm] = w0.w;
        Ws[lk + 0][lm + 32] = w1.x; Ws[lk + 1][lm + 32] = w1.y;
        Ws[lk + 2][lm + 32] = w1.z; Ws[lk + 3][lm + 32] = w1.w;

        __syncthreads();

        #pragma unroll
        for (int k = 0; k < BK; k++) {
            const float4 av = *(const float4*)&As[k][ty * 4];
            const float4 wv = *(const float4*)&Ws[k][tx * 4];
            const float am[4] = {av.x, av.y, av.z, av.w};
            const float wn[4] = {wv.x, wv.y, wv.z, wv.w};
            #pragma unroll
            for (int r = 0; r < 4; r++)
                #pragma unroll
                for (int c = 0; c < 4; c++)
                    acc[r][c] = fmaf(am[r], wn[c], acc[r][c]);
        }
    }

    #pragma unroll
    for (int r = 0; r < 4; r++) {
        float4 v = make_float4(acc[r][0], acc[r][1], acc[r][2], acc[r][3]);
        *(float4*)&C[(m0 + ty * 4 + r) * TIN + i0 + tx * 4] = v;
    }
}

// ---------------------------------------------------------------------------
// Inputs (metadata order):
//   d_in[0] surv_steps  float32 [32,64,512]  (1048576 elems)
//   d_in[1] time_bg     float32 [512]
//   d_in[2] time_in     float32 [256]
//   d_in[3] bandwidth   float32 [1]
//   d_in[4] single_time int     (0 -> einsum path)
// Output: float32 [32,64,256] = [2048,256]
// ---------------------------------------------------------------------------
extern "C" void kernel_launch(void* const* d_in, const int* in_sizes, int n_in,
                              void* d_out, int out_size) {
    const float* surv      = (const float*)d_in[0];
    const float* time_bg   = (const float*)d_in[1];
    const float* time_in   = (const float*)d_in[2];
    const float* bandwidth = (const float*)d_in[3];
    float*       out       = (float*)d_out;

    softmin_weights_kernel<<<TIN, 256>>>(time_bg, time_in, bandwidth);

    dim3 grid(TIN / BI, MROWS / BM);
    smoother_gemm_kernel<<<grid, 256>>>(surv, out);
}

// round 3
// speedup vs baseline: 2.2059x; 2.2059x over previous
#include <cuda_runtime.h>
#include <cuda_bf16.h>
#include <mma.h>
#include <cstdint>

using namespace nvcuda;

#define TBG 512
#define TIN 256
#define MROWS 2048   // B*N = 32*64

// bf16 copies of the GEMM operands (RN-rounded)
__device__ __align__(128) __nv_bfloat16 g_ab[MROWS * TBG];  // surv as bf16
__device__ __align__(128) __nv_bfloat16 g_wb[TIN * TBG];    // softmin weights bf16

// ===========================================================================
// Kernel 1 (fused prep):
//   blocks [0,256):    softmin weights  -> g_wb (bf16, RN)
//   blocks [256,1280): surv fp32 -> bf16 -> g_ab (RN), 4 elems/thread
// ===========================================================================
__global__ void prep_kernel(const float* __restrict__ surv,
                            const float* __restrict__ time_bg,
                            const float* __restrict__ time_in,
                            const float* __restrict__ bandwidth) {
    const int tid = threadIdx.x;

    if (blockIdx.x >= 256) {
        const int idx = (blockIdx.x - 256) * 256 + tid;   // float4 index
        const float4 v = reinterpret_cast<const float4*>(surv)[idx];
        __nv_bfloat162 p0 = __floats2bfloat162_rn(v.x, v.y);
        __nv_bfloat162 p1 = __floats2bfloat162_rn(v.z, v.w);
        uint2 o;
        o.x = *reinterpret_cast<unsigned int*>(&p0);
        o.y = *reinterpret_cast<unsigned int*>(&p1);
        reinterpret_cast<uint2*>(g_ab)[idx] = o;
        return;
    }

    __shared__ float s_red[8];
    __shared__ float s_bcast;

    const int i  = blockIdx.x;
    const float b  = fmaxf(bandwidth[0], 1e-6f);
    const float ti = time_in[i];

    const float x0 = b * fabsf(time_bg[tid]       - ti);
    const float x1 = b * fabsf(time_bg[tid + 256] - ti);

    float mn = fminf(x0, x1);
    #pragma unroll
    for (int o = 16; o > 0; o >>= 1)
        mn = fminf(mn, __shfl_xor_sync(0xffffffffu, mn, o));
    if ((tid & 31) == 0) s_red[tid >> 5] = mn;
    __syncthreads();
    if (tid == 0) {
        float v = s_red[0];
        #pragma unroll
        for (int w = 1; w < 8; w++) v = fminf(v, s_red[w]);
        s_bcast = v;
    }
    __syncthreads();
    const float xmin = s_bcast;

    const float e0 = __expf(xmin - x0);
    const float e1 = __expf(xmin - x1);

    float sm = e0 + e1;
    #pragma unroll
    for (int o = 16; o > 0; o >>= 1)
        sm += __shfl_xor_sync(0xffffffffu, sm, o);
    if ((tid & 31) == 0) s_red[tid >> 5] = sm;
    __syncthreads();
    if (tid == 0) {
        float v = 0.0f;
        #pragma unroll
        for (int w = 0; w < 8; w++) v += s_red[w];
        s_bcast = v;
    }
    __syncthreads();

    const float inv = 1.0f / s_bcast;
    g_wb[i * TBG + tid]       = __float2bfloat16(e0 * inv);
    g_wb[i * TBG + tid + 256] = __float2bfloat16(e1 * inv);
}

// ===========================================================================
// Kernel 2: WMMA bf16 GEMM  C[2048,256] = Abf[2048,512] * Wbf[256,512]^T
//   CTA tile 64x64, 4 warps (2x2), warp tile 32x32 (2x2 wmma frags).
//   K chunk = 32, 2-stage cp.async double buffer.
//   Grid: (256/64, 2048/64) = (4,32) = 128 CTAs ~ 1/SM.
// ===========================================================================
#define BK    32
#define LDS   40   // padded leading dim (elements): conflict-free ldmatrix

__device__ __forceinline__ void cp_async16(void* smem_dst, const void* gmem_src) {
    uint32_t a;
    asm("{ .reg .u64 t; cvta.to.shared.u64 t, %1; cvt.u32.u64 %0, t; }"
        : "=r"(a) : "l"(smem_dst));
    asm volatile("cp.async.cg.shared.global [%0], [%1], 16;" :: "r"(a), "l"(gmem_src));
}
__device__ __forceinline__ void cp_commit() {
    asm volatile("cp.async.commit_group;");
}
template <int N>
__device__ __forceinline__ void cp_wait() {
    asm volatile("cp.async.wait_group %0;" :: "n"(N));
}

__global__ void __launch_bounds__(128, 1)
wmma_gemm_kernel(float* __restrict__ C) {
    __shared__ __nv_bfloat16 As[2][64 * LDS];
    __shared__ __nv_bfloat16 Bs[2][64 * LDS];

    const int tid = threadIdx.x;
    const int wid = tid >> 5;
    const int wm  = wid >> 1;          // 0..1 (m direction)
    const int wn  = wid & 1;           // 0..1 (n direction)

    const int m0 = blockIdx.y * 64;
    const int i0 = blockIdx.x * 64;

    const __nv_bfloat16* Ag = g_ab + (size_t)m0 * TBG;
    const __nv_bfloat16* Bg = g_wb + (size_t)i0 * TBG;

    // cp.async mapping: 256 16B-chunks per 64x32 tile, 128 threads x 2.
    // idx = it*128 + tid : row = idx/4 (0..63), col chunk = idx%4 (8 elems each)
    auto load_chunk = [&](int buf, int k0) {
        #pragma unroll
        for (int it = 0; it < 2; it++) {
            const int idx = it * 128 + tid;
            const int r = idx >> 2;
            const int c = (idx & 3) << 3;
            cp_async16(&As[buf][r * LDS + c], Ag + (size_t)r * TBG + k0 + c);
            cp_async16(&Bs[buf][r * LDS + c], Bg + (size_t)r * TBG + k0 + c);
        }
        cp_commit();
    };

    wmma::fragment<wmma::accumulator, 16, 16, 16, float> acc[2][2];
    #pragma unroll
    for (int i = 0; i < 2; i++)
        #pragma unroll
        for (int j = 0; j < 2; j++)
            wmma::fill_fragment(acc[i][j], 0.0f);

    load_chunk(0, 0);

    const int NCHUNK = TBG / BK;   // 16
    #pragma unroll 1
    for (int c = 0; c < NCHUNK; c++) {
        const int buf = c & 1;
        if (c + 1 < NCHUNK) {
            load_chunk(buf ^ 1, (c + 1) * BK);
            cp_wait<1>();
        } else {
            cp_wait<0>();
        }
        __syncthreads();

        #pragma unroll
        for (int kk = 0; kk < BK; kk += 16) {
            wmma::fragment<wmma::matrix_a, 16, 16, 16, __nv_bfloat16, wmma::row_major> af[2];
            wmma::fragment<wmma::matrix_b, 16, 16, 16, __nv_bfloat16, wmma::col_major> bf[2];
            #pragma unroll
            for (int i = 0; i < 2; i++)
                wmma::load_matrix_sync(af[i], &As[buf][(wm * 32 + i * 16) * LDS + kk], LDS);
            #pragma unroll
            for (int j = 0; j < 2; j++)
                wmma::load_matrix_sync(bf[j], &Bs[buf][(wn * 32 + j * 16) * LDS + kk], LDS);
            #pragma unroll
            for (int i = 0; i < 2; i++)
                #pragma unroll
                for (int j = 0; j < 2; j++)
                    wmma::mma_sync(acc[i][j], af[i], bf[j], acc[i][j]);
        }
        __syncthreads();
    }

    #pragma unroll
    for (int i = 0; i < 2; i++)
        #pragma unroll
        for (int j = 0; j < 2; j++) {
            float* cp = C + (size_t)(m0 + wm * 32 + i * 16) * TIN + i0 + wn * 32 + j * 16;
            wmma::store_matrix_sync(cp, acc[i][j], TIN, wmma::mem_row_major);
        }
}

// ===========================================================================
// Host side
// ===========================================================================
extern "C" void kernel_launch(void* const* d_in, const int* in_sizes, int n_in,
                              void* d_out, int out_size) {
    const float* surv      = (const float*)d_in[0];
    const float* time_bg   = (const float*)d_in[1];
    const float* time_in   = (const float*)d_in[2];
    const float* bandwidth = (const float*)d_in[3];
    float*       out       = (float*)d_out;

    prep_kernel<<<1280, 256>>>(surv, time_bg, time_in, bandwidth);

    dim3 grid(TIN / 64, MROWS / 64);
    wmma_gemm_kernel<<<grid, 128>>>(out);
}

// round 8
// speedup vs baseline: 2.3839x; 1.0807x over previous
#include <cuda_runtime.h>
#include <cuda_bf16.h>
#include <mma.h>
#include <cstdint>

using namespace nvcuda;

#define TBG   512
#define TIN   256
#define MROWS 2048      // B*N = 32*64

#define LDW   520       // padded leading dim (elements) for both smem tiles

// smem layout (dynamic):
//   As : 64 x LDW bf16   (A tile,   66560 B)
//   Ws : 64 x LDW bf16   (W tile,   66560 B)
//   tb : 512 float       (time_bg,   2048 B)
#define AS_BYTES (64 * LDW * 2)
#define SMEM_TOTAL (2 * AS_BYTES + 512 * 4)

__global__ void __launch_bounds__(256, 1)
fused_kernel(const float* __restrict__ surv,
             const float* __restrict__ time_bg,
             const float* __restrict__ time_in,
             const float* __restrict__ bandwidth,
             float* __restrict__ C) {
    extern __shared__ char smem[];
    __nv_bfloat16* As = reinterpret_cast<__nv_bfloat16*>(smem);
    __nv_bfloat16* Ws = reinterpret_cast<__nv_bfloat16*>(smem + AS_BYTES);
    float*         tb = reinterpret_cast<float*>(smem + 2 * AS_BYTES);

    const int tid = threadIdx.x;
    const int wid = tid >> 5;
    const int lid = tid & 31;

    const int i0 = blockIdx.x * 64;   // output col block (T_in)
    const int m0 = blockIdx.y * 64;   // output row block (B*N)

    // ---- stage time_bg into smem (needed by W phase) ----
    tb[tid]       = time_bg[tid];
    tb[tid + 256] = time_bg[tid + 256];

    // ---- Phase A: load A tile [64 x 512] fp32 -> bf16 smem ----
    // 8192 float4 total, 32 per thread. idx = it*256 + tid; row = idx/128.
    {
        const float* Ag = surv + (size_t)m0 * TBG;
        #pragma unroll 8
        for (int it = 0; it < 32; it++) {
            const int idx = it * 256 + tid;
            const int r   = idx >> 7;          // 0..63
            const int c4  = idx & 127;         // float4 within row
            const float4 v = *reinterpret_cast<const float4*>(Ag + (size_t)r * TBG + c4 * 4);
            __nv_bfloat162 p0 = __floats2bfloat162_rn(v.x, v.y);
            __nv_bfloat162 p1 = __floats2bfloat162_rn(v.z, v.w);
            uint2 o;
            o.x = *reinterpret_cast<unsigned int*>(&p0);
            o.y = *reinterpret_cast<unsigned int*>(&p1);
            *reinterpret_cast<uint2*>(&As[r * LDW + c4 * 4]) = o;
        }
    }
    __syncthreads();   // tb ready (and As in flight; full barrier also orders As)

    // ---- Phase W: softmin weights for 64 i's, 8 i's per warp ----
    {
        const float b = fmaxf(bandwidth[0], 1e-6f);
        #pragma unroll 1
        for (int ii = 0; ii < 8; ii++) {
            const int i  = wid * 8 + ii;           // local i 0..63
            const float ti = time_in[i0 + i];

            float x[16];
            float mn = 3.4e38f;
            #pragma unroll
            for (int j = 0; j < 16; j++) {
                x[j] = b * fabsf(tb[j * 32 + lid] - ti);
                mn = fminf(mn, x[j]);
            }
            #pragma unroll
            for (int o = 16; o > 0; o >>= 1)
                mn = fminf(mn, __shfl_xor_sync(0xffffffffu, mn, o));

            float e[16];
            float sm = 0.0f;
            #pragma unroll
            for (int j = 0; j < 16; j++) {
                e[j] = __expf(mn - x[j]);
                sm += e[j];
            }
            #pragma unroll
            for (int o = 16; o > 0; o >>= 1)
                sm += __shfl_xor_sync(0xffffffffu, sm, o);

            const float inv = 1.0f / sm;
            #pragma unroll
            for (int j = 0; j < 16; j++)
                Ws[i * LDW + j * 32 + lid] = __float2bfloat16(e[j] * inv);
        }
    }
    __syncthreads();

    // ---- Phase MMA: warp grid 2(m) x 4(i), warp tile 32m x 16i ----
    {
        const int wm = wid & 1;        // 0..1
        const int wi = wid >> 1;       // 0..3

        wmma::fragment<wmma::accumulator, 16, 16, 16, float> acc[2];
        wmma::fill_fragment(acc[0], 0.0f);
        wmma::fill_fragment(acc[1], 0.0f);

        const __nv_bfloat16* a_base = &As[(wm * 32) * LDW];
        const __nv_bfloat16* b_base = &Ws[(wi * 16) * LDW];

        #pragma unroll 4
        for (int kk = 0; kk < TBG; kk += 16) {
            wmma::fragment<wmma::matrix_a, 16, 16, 16, __nv_bfloat16, wmma::row_major> af0, af1;
            wmma::fragment<wmma::matrix_b, 16, 16, 16, __nv_bfloat16, wmma::col_major> bf;
            wmma::load_matrix_sync(af0, a_base + kk, LDW);
            wmma::load_matrix_sync(af1, a_base + 16 * LDW + kk, LDW);
            wmma::load_matrix_sync(bf,  b_base + kk, LDW);
            wmma::mma_sync(acc[0], af0, bf, acc[0]);
            wmma::mma_sync(acc[1], af1, bf, acc[1]);
        }

        float* cp0 = C + (size_t)(m0 + wm * 32)      * TIN + i0 + wi * 16;
        float* cp1 = C + (size_t)(m0 + wm * 32 + 16) * TIN + i0 + wi * 16;
        wmma::store_matrix_sync(cp0, acc[0], TIN, wmma::mem_row_major);
        wmma::store_matrix_sync(cp1, acc[1], TIN, wmma::mem_row_major);
    }
}

// ===========================================================================
extern "C" void kernel_launch(void* const* d_in, const int* in_sizes, int n_in,
                              void* d_out, int out_size) {
    const float* surv      = (const float*)d_in[0];
    const float* time_bg   = (const float*)d_in[1];
    const float* time_in   = (const float*)d_in[2];
    const float* bandwidth = (const float*)d_in[3];
    float*       out       = (float*)d_out;

    static bool attr_done = false;
    if (!attr_done) {
        cudaFuncSetAttribute(fused_kernel,
                             cudaFuncAttributeMaxDynamicSharedMemorySize, SMEM_TOTAL);
        attr_done = true;
    }

    dim3 grid(TIN / 64, MROWS / 64);   // (4, 32) = 128 CTAs
    fused_kernel<<<grid, 256, SMEM_TOTAL>>>(surv, time_bg, time_in, bandwidth, out);
}